// round 15
// baseline (speedup 1.0000x reference)
#include <cuda_runtime.h>

#define BATCH   8
#define NPTS    8192
#define CIN     64
#define CMID    128
#define NSAMP   2048
#define KNNK    32
#define NGRP    (BATCH*NSAMP)        /* 16384 */
#define GELEMS  (CMID*KNNK)          /* 4096  */
#define PELEMS  (CMID*NSAMP)         /* 262144 */

#define XS_STRIDE 132                /* padded row stride (floats) */

// -------- scratch (static device globals; no allocation APIs) --------
__device__ float  g_bufA[(size_t)NGRP * GELEMS];   // 268 MB
__device__ float  g_bufB[(size_t)NGRP * GELEMS];   // 268 MB
__device__ float  g_bufP[(size_t)BATCH * PELEMS];  // 8.4 MB
__device__ float  g_bufD[(size_t)BATCH * PELEMS];  // 8.4 MB
__device__ int    g_fps[NGRP];
__device__ int    g_knn[NGRP * KNNK];
__device__ float2 g_wt2[9 * 16384];                // transposed+duplicated W

// Bit-exact match to XLA's un-contracted  (dx*dx + dy*dy) + dz*dz
__device__ __forceinline__ float sqdist(float dx, float dy, float dz)
{
    float a = __fmul_rn(dx, dx);
    float b = __fmul_rn(dy, dy);
    float c = __fmul_rn(dz, dz);
    return __fadd_rn(__fadd_rn(a, b), c);
}

__device__ __forceinline__ unsigned redux_max_u32(unsigned v)
{
    unsigned r;
    asm("redux.sync.max.u32 %0, %1, 0xffffffff;" : "=r"(r) : "r"(v));
    return r;
}

#define FFMA2(acc, a, b) \
    asm("fma.rn.f32x2 %0, %1, %2, %3;" : "=l"(acc) : "l"(a), "l"(b), "l"(acc))
#define ADD2(d, a, b) \
    asm("add.rn.f32x2 %0, %1, %2;" : "=l"(d) : "l"(a), "l"(b))
#define MUL2(d, a, b) \
    asm("mul.rn.f32x2 %0, %1, %2;" : "=l"(d) : "l"(a), "l"(b))
#define PACK2(d, lo, hi) \
    asm("mov.b64 %0, {%1, %2};" : "=l"(d) : "r"(__float_as_uint(lo)), "r"(__float_as_uint(hi)))
#define PACKDUP(d, f) \
    asm("mov.b64 %0, {%1, %1};" : "=l"(d) : "r"(__float_as_uint(f)))
#define UNPACK64(lo, hi, v) \
    asm("mov.b64 {%0, %1}, %2;" : "=r"(lo), "=r"(hi) : "l"(v))

// ====================================================================
// Weight pre-transform: Wt2[s][c][o] = {W_s[o][c], W_s[o][c]}
// ====================================================================
struct WPtrs { const float* w[9]; };
__global__ __launch_bounds__(256) void wtrans_kernel(WPtrs p, float2* __restrict__ out)
{
    int idx = blockIdx.x * 256 + threadIdx.x;         // 9*16384 total
    int s = idx >> 14, r = idx & 16383;
    int o = r >> 7, c = r & 127;
    float w = p.w[s][o * 128 + c];
    out[(s << 14) + c * 128 + o] = make_float2(w, w);
}

// ====================================================================
// FPS: one block/batch, 512 threads, 16 pts/thread (8 packed slots),
// 1 barrier/step. Packed f32x2 distance math (bit-exact).
// ====================================================================
__global__ __launch_bounds__(512) void fps_kernel(const float* __restrict__ xyz,
                                                  float* __restrict__ newxyz,
                                                  int* __restrict__ fpsIdx)
{
    extern __shared__ float fsm[];
    float* sx = fsm;
    float* sy = fsm + NPTS;
    float* sz = fsm + 2*NPTS;
    float* s_val2 = fsm + 3*NPTS;           // [2][16]
    int*   s_idx2 = (int*)(fsm + 3*NPTS + 32);

    const int b = blockIdx.x;
    const int t = threadIdx.x;
    const int lane = t & 31;
    const int warp = t >> 5;                // 0..15
    const float* base = xyz + (size_t)b * NPTS * 3;

    unsigned long long ppx[8], ppy[8], ppz[8], pdd[8];
    float fx0 = 0.f, fy0 = 0.f, fz0 = 0.f;
#pragma unroll
    for (int u = 0; u < 8; u++) {
        int p0 = (2*u) * 512 + t;
        int p1 = (2*u + 1) * 512 + t;
        float x0 = base[p0*3+0], y0 = base[p0*3+1], z0 = base[p0*3+2];
        float x1 = base[p1*3+0], y1 = base[p1*3+1], z1 = base[p1*3+2];
        PACK2(ppx[u], x0, x1);
        PACK2(ppy[u], y0, y1);
        PACK2(ppz[u], z0, z1);
        sx[p0] = x0; sy[p0] = y0; sz[p0] = z0;
        sx[p1] = x1; sy[p1] = y1; sz[p1] = z1;
        PACKDUP(pdd[u], 1e10f);
        if (u == 0) { fx0 = x0; fy0 = y0; fz0 = z0; }
    }

    if (t == 0) {
        fpsIdx[b*NSAMP] = 0;
        newxyz[(size_t)b*NSAMP*3 + 0] = fx0;
        newxyz[(size_t)b*NSAMP*3 + 1] = fy0;
        newxyz[(size_t)b*NSAMP*3 + 2] = fz0;
    }
    __syncthreads();

    int w = 0;
    for (int s = 1; s < NSAMP; s++) {
        unsigned long long nqx2, nqy2, nqz2;
        {
            float nqx = -sx[w], nqy = -sy[w], nqz = -sz[w];
            PACKDUP(nqx2, nqx); PACKDUP(nqy2, nqy); PACKDUP(nqz2, nqz);
        }
        float bv = -1.0f; int bj = 0;
#pragma unroll
        for (int u = 0; u < 8; u++) {
            unsigned long long dx, dy, dz, ss;
            ADD2(dx, ppx[u], nqx2);       // px - qx
            ADD2(dy, ppy[u], nqy2);
            ADD2(dz, ppz[u], nqz2);
            MUL2(dx, dx, dx);
            MUL2(dy, dy, dy);
            MUL2(dz, dz, dz);
            ADD2(ss, dx, dy);
            ADD2(ss, ss, dz);
            unsigned d0b, d1b, e0b, e1b;
            UNPACK64(d0b, d1b, ss);
            UNPACK64(e0b, e1b, pdd[u]);
            float e0 = fminf(__uint_as_float(e0b), __uint_as_float(d0b));
            float e1 = fminf(__uint_as_float(e1b), __uint_as_float(d1b));
            PACK2(pdd[u], e0, e1);
            if (e0 > bv) { bv = e0; bj = 2*u; }
            if (e1 > bv) { bv = e1; bj = 2*u + 1; }
        }
        int gi = (bj << 9) | t;
        unsigned ub = __float_as_uint(bv);
        unsigned mx = redux_max_u32(ub);
        unsigned bl = __ballot_sync(0xffffffffu, ub == mx);
        int src = __ffs(bl) - 1;
        int wgi = __shfl_sync(0xffffffffu, gi, src);

        const int par = (s & 1) * 16;
        if (lane == 0) { s_val2[par + warp] = __uint_as_float(mx); s_idx2[par + warp] = wgi; }
        __syncthreads();

        unsigned v2 = (lane < 16) ? __float_as_uint(s_val2[par + lane]) : 0u;
        int      i2 = (lane < 16) ? s_idx2[par + lane] : 0;
        unsigned m2 = redux_max_u32(v2);
        unsigned b2 = __ballot_sync(0xffffffffu, v2 == m2);
        int s2 = __ffs(b2) - 1;
        w = __shfl_sync(0xffffffffu, i2, s2);

        if (t == 0) {
            fpsIdx[b*NSAMP + s] = w;
            size_t o = ((size_t)b*NSAMP + s)*3;
            newxyz[o+0] = sx[w]; newxyz[o+1] = sy[w]; newxyz[o+2] = sz[w];
        }
    }
}

// ====================================================================
// KNN: 256 blocks, warp-per-sample sorted top-32.
// ====================================================================
__global__ __launch_bounds__(256) void knn_kernel(const float* __restrict__ xyz,
                                                  const float* __restrict__ newxyz,
                                                  int* __restrict__ knnIdx)
{
    extern __shared__ float sm[];
    float* sx = sm; float* sy = sm + NPTS; float* sz = sm + 2*NPTS;
    const int b    = blockIdx.x >> 5;
    const int tile = blockIdx.x & 31;
    const float* base = xyz + (size_t)b * NPTS * 3;
    for (int i = threadIdx.x; i < NPTS; i += 256) {
        sx[i] = base[i*3+0]; sy[i] = base[i*3+1]; sz[i] = base[i*3+2];
    }
    __syncthreads();

    const int lane = threadIdx.x & 31;
    const int warp = threadIdx.x >> 5;

    for (int rep = 0; rep < 8; rep++) {
        const int s = tile*64 + warp*8 + rep;
        const float* q = newxyz + ((size_t)b*NSAMP + s)*3;
        const float qx = q[0], qy = q[1], qz = q[2];
        float lval = 1e30f; int lidx = 0;
        float thr  = 1e30f;

        for (int j0 = 0; j0 < NPTS/32; j0++) {
            const int p = j0*32 + lane;
            float d = sqdist(sx[p]-qx, sy[p]-qy, sz[p]-qz);
            unsigned m = __ballot_sync(0xffffffffu, d < thr);
            if (m) {
                while (m) {
                    int src = __ffs(m) - 1; m &= m - 1;
                    float cd = __shfl_sync(0xffffffffu, d, src);
                    int   cj = __shfl_sync(0xffffffffu, p, src);
                    float pv = __shfl_up_sync(0xffffffffu, lval, 1);
                    int   pi = __shfl_up_sync(0xffffffffu, lidx, 1);
                    bool shift  = lval > cd;
                    bool pshift = (lane > 0) && (pv > cd);
                    lval = shift ? (pshift ? pv : cd) : lval;
                    lidx = shift ? (pshift ? pi : cj) : lidx;
                }
                thr = __shfl_sync(0xffffffffu, lval, 31);
            }
        }
        knnIdx[((size_t)b*NSAMP + s)*KNNK + lane] = lidx;
    }
}

// ====================================================================
// Fused conv1x1 + BN + (residual) + ReLU. FFMA2 col-pairs (R8 tile),
// W staged in smem PRE-DUPLICATED {w,w} (32-row quarters) -> no
// PACKDUP in the mainloop: 2 LDS(X) + 4 LDS(W) + 32 FFMA2 per kc.
// Thread tx=tid&15 owns cols {tx*4..+3} and {64+tx*4..+3}; ty=tid>>4.
// ====================================================================
template<int GATHER, int POOL>
__global__ __launch_bounds__(256, 2) void conv_bn_t(
    const float* __restrict__ X,
    const float* __restrict__ feat, const int* __restrict__ knnIdx, const int* __restrict__ fpsIdx,
    const float2* __restrict__ Wt2,
    const float* __restrict__ gam, const float* __restrict__ bet,
    const float* __restrict__ mu,  const float* __restrict__ var,
    const float* __restrict__ R,   float* __restrict__ Y,
    int kls)
{
    extern __shared__ float sm[];
    float* Xs      = sm;                       // [128][132]
    float* Ws      = sm + 128*XS_STRIDE;       // [32][128 float2] = 32 KB quarter
    float* s_scale = Ws + 32*256;
    float* s_shift = s_scale + 128;

    const int tid  = threadIdx.x;
    const int klen = 1 << kls;
    const int n0   = blockIdx.x << 7;

    if (GATHER) {
        const int gbase = n0 >> 5;                  // kls == 5 in gather mode
        const int b = gbase >> 11;
        const float* fb = feat + (size_t)b * NPTS * CIN;
        const int cc = tid & 63, jj = tid >> 6;
        for (int it = 0; it < 32; it++) {
            int col = it*4 + jj;
            int g = gbase + (col >> 5), k = col & 31;
            int p = __ldg(&knnIdx[g*KNNK + k]);
            Xs[cc*XS_STRIDE + col] = fb[p*CIN + cc];
        }
        {
            int g = gbase + jj;
            float v = fb[__ldg(&fpsIdx[g])*CIN + cc];
            float4* row = (float4*)(Xs + (cc + CIN)*XS_STRIDE + jj*32);
            float4 vv = make_float4(v, v, v, v);
#pragma unroll
            for (int k4 = 0; k4 < 8; k4++) row[k4] = vv;
        }
    } else {
        for (int idx = tid; idx < 16384; idx += 256) {
            int c = idx >> 7, col = idx & 127;
            int n = n0 + col;
            int g = n >> kls, k = n & (klen-1);
            Xs[c*XS_STRIDE + col] = X[((g << 7) + c) * klen + k];
        }
    }
    if (tid < 128) {
        float sc = gam[tid] / sqrtf(var[tid] + 1e-5f);
        s_scale[tid] = sc;
        s_shift[tid] = bet[tid] - mu[tid] * sc;
    }

    const int tx = tid & 15, ty = tid >> 4;
    unsigned long long acc[8][4];               // [o][colpair]
#pragma unroll
    for (int i = 0; i < 8; i++)
#pragma unroll
        for (int j = 0; j < 4; j++) acc[i][j] = 0ull;

    const float* XsC = Xs + tx*4;

    for (int q = 0; q < 4; q++) {
        __syncthreads();     // q=0: covers X/scale writes; else: Ws reuse
        {   // stage W quarter: rows q*32 .. q*32+31 (4096 float2 = 32 KB)
            const float4* src = (const float4*)(Wt2 + q*32*128);
            float4*       dst = (float4*)Ws;
#pragma unroll
            for (int i = 0; i < 8; i++) dst[tid + i*256] = src[tid + i*256];
        }
        __syncthreads();

#pragma unroll 4
        for (int kc2 = 0; kc2 < 32; kc2++) {
            const int kc = q*32 + kc2;
            ulonglong2 xa = *(const ulonglong2*)(XsC + kc*XS_STRIDE);        // cols tx*4..+3
            ulonglong2 xb = *(const ulonglong2*)(XsC + kc*XS_STRIDE + 64);   // cols 64+tx*4..+3
            const ulonglong2* wrow = (const ulonglong2*)(Ws + kc2*256 + ty*16);
            ulonglong2 wp0 = wrow[0];
            ulonglong2 wp1 = wrow[1];
            ulonglong2 wp2 = wrow[2];
            ulonglong2 wp3 = wrow[3];
            unsigned long long wv[8] = {wp0.x, wp0.y, wp1.x, wp1.y, wp2.x, wp2.y, wp3.x, wp3.y};
            unsigned long long xp[4] = {xa.x, xa.y, xb.x, xb.y};
#pragma unroll
            for (int i = 0; i < 8; i++)
#pragma unroll
                for (int j = 0; j < 4; j++)
                    FFMA2(acc[i][j], wv[i], xp[j]);
        }
    }

    const int ncolA = n0 + tx*4;
    const int ncolB = ncolA + 64;
    const int gA = ncolA >> kls, kA = ncolA & (klen-1);
    const int gB = ncolB >> kls, kB = ncolB & (klen-1);
#pragma unroll
    for (int i = 0; i < 8; i++) {
        const int o = ty*8 + i;
        const float sc = s_scale[o], sh = s_shift[o];
        const int addrA = ((gA << 7) + o) * klen + kA;
        const int addrB = ((gB << 7) + o) * klen + kB;
        float v[8];
#pragma unroll
        for (int j = 0; j < 4; j++) {
            unsigned lo, hi;
            UNPACK64(lo, hi, acc[i][j]);
            v[2*j]   = __uint_as_float(lo);
            v[2*j+1] = __uint_as_float(hi);
        }
#pragma unroll
        for (int j = 0; j < 8; j++) v[j] = fmaf(v[j], sc, sh);
        if (R) {
            float4 rA = *(const float4*)(R + addrA);
            float4 rB = *(const float4*)(R + addrB);
            v[0]+=rA.x; v[1]+=rA.y; v[2]+=rA.z; v[3]+=rA.w;
            v[4]+=rB.x; v[5]+=rB.y; v[6]+=rB.z; v[7]+=rB.w;
        }
#pragma unroll
        for (int j = 0; j < 8; j++) v[j] = fmaxf(v[j], 0.f);

        if (POOL) {
            // klen==32: group A = 32 cols covered by tx-octet {0-7} or {8-15}
            float mA = fmaxf(fmaxf(v[0],v[1]), fmaxf(v[2],v[3]));
            float mB = fmaxf(fmaxf(v[4],v[5]), fmaxf(v[6],v[7]));
            mA = fmaxf(mA, __shfl_xor_sync(0xffffffffu, mA, 1));
            mB = fmaxf(mB, __shfl_xor_sync(0xffffffffu, mB, 1));
            mA = fmaxf(mA, __shfl_xor_sync(0xffffffffu, mA, 2));
            mB = fmaxf(mB, __shfl_xor_sync(0xffffffffu, mB, 2));
            mA = fmaxf(mA, __shfl_xor_sync(0xffffffffu, mA, 4));
            mB = fmaxf(mB, __shfl_xor_sync(0xffffffffu, mB, 4));
            if ((tx & 7) == 0) {
                int bbA = gA >> 11, sA = gA & 2047;
                int bbB = gB >> 11, sB = gB & 2047;
                Y[((bbA << 7) + o) * 2048 + sA] = mA;
                Y[((bbB << 7) + o) * 2048 + sB] = mB;
            }
        } else {
            *(float4*)(Y + addrA) = make_float4(v[0],v[1],v[2],v[3]);
            *(float4*)(Y + addrB) = make_float4(v[4],v[5],v[6],v[7]);
        }
    }
}

// ====================================================================
extern "C" void kernel_launch(void* const* d_in, const int* in_sizes, int n_in,
                              void* d_out, int out_size)
{
    // setup_inputs() dict-insertion order
    const float* xyz    = (const float*)d_in[0];
    const float* feat   = (const float*)d_in[1];
    const float* te_w   = (const float*)d_in[2];
    const float* te_g   = (const float*)d_in[3];
    const float* te_b   = (const float*)d_in[4];
    const float* te_m   = (const float*)d_in[5];
    const float* te_v   = (const float*)d_in[6];
    const float* pre_w1 = (const float*)d_in[7];
    const float* pre_w2 = (const float*)d_in[8];
    const float* pre_g1 = (const float*)d_in[9];
    const float* pre_g2 = (const float*)d_in[10];
    const float* pre_b1 = (const float*)d_in[11];
    const float* pre_b2 = (const float*)d_in[12];
    const float* pre_m1 = (const float*)d_in[13];
    const float* pre_m2 = (const float*)d_in[14];
    const float* pre_v1 = (const float*)d_in[15];
    const float* pre_v2 = (const float*)d_in[16];
    const float* pos_w1 = (const float*)d_in[17];
    const float* pos_w2 = (const float*)d_in[18];
    const float* pos_g1 = (const float*)d_in[19];
    const float* pos_g2 = (const float*)d_in[20];
    const float* pos_b1 = (const float*)d_in[21];
    const float* pos_b2 = (const float*)d_in[22];
    const float* pos_m1 = (const float*)d_in[23];
    const float* pos_m2 = (const float*)d_in[24];
    const float* pos_v1 = (const float*)d_in[25];
    const float* pos_v2 = (const float*)d_in[26];

    float* out_xyz = (float*)d_out;                    // (8,2048,3)
    float* out_x   = (float*)d_out + BATCH*NSAMP*3;    // (8,128,2048)

    float *A, *Bb, *P, *D; int *fp, *kn; float2 *wt;
    cudaGetSymbolAddress((void**)&A,  g_bufA);
    cudaGetSymbolAddress((void**)&Bb, g_bufB);
    cudaGetSymbolAddress((void**)&P,  g_bufP);
    cudaGetSymbolAddress((void**)&D,  g_bufD);
    cudaGetSymbolAddress((void**)&fp, g_fps);
    cudaGetSymbolAddress((void**)&kn, g_knn);
    cudaGetSymbolAddress((void**)&wt, g_wt2);

    const int FPS_SMEM  = (3*NPTS + 64) * 4;                    // ~98.5 KB
    const int KNN_SMEM  = 3 * NPTS * 4;                         // 96 KB
    const int CONV_SMEM = (128*XS_STRIDE + 32*256 + 256) * 4;   // 101376 B
    cudaFuncSetAttribute(fps_kernel,      cudaFuncAttributeMaxDynamicSharedMemorySize, FPS_SMEM);
    cudaFuncSetAttribute(knn_kernel,      cudaFuncAttributeMaxDynamicSharedMemorySize, KNN_SMEM);
    cudaFuncSetAttribute(conv_bn_t<0,0>,  cudaFuncAttributeMaxDynamicSharedMemorySize, CONV_SMEM);
    cudaFuncSetAttribute(conv_bn_t<1,0>,  cudaFuncAttributeMaxDynamicSharedMemorySize, CONV_SMEM);
    cudaFuncSetAttribute(conv_bn_t<0,1>,  cudaFuncAttributeMaxDynamicSharedMemorySize, CONV_SMEM);

    // weight pre-transform (stage order: te, pw1[0], pw2[0], pw1[1], pw2[1], qw1[0], qw2[0], qw1[1], qw2[1])
    WPtrs wp;
    wp.w[0] = te_w;
    wp.w[1] = pre_w1;          wp.w[2] = pre_w2;
    wp.w[3] = pre_w1 + 16384;  wp.w[4] = pre_w2 + 16384;
    wp.w[5] = pos_w1;          wp.w[6] = pos_w2;
    wp.w[7] = pos_w1 + 16384;  wp.w[8] = pos_w2 + 16384;
    wtrans_kernel<<<(9*16384)/256, 256>>>(wp, wt);

    fps_kernel<<<BATCH, 512, FPS_SMEM>>>(xyz, out_xyz, fp);
    knn_kernel<<<256, 256, KNN_SMEM>>>(xyz, out_xyz, kn);

    // te (gather fused) + 2 pre res-blocks; 524288 cols, kls=5
    conv_bn_t<1,0><<<4096, 256, CONV_SMEM>>>(nullptr, feat, kn, fp, wt + 0*16384, te_g, te_b, te_m, te_v, nullptr, Bb, 5);
    conv_bn_t<0,0><<<4096, 256, CONV_SMEM>>>(Bb, nullptr, nullptr, nullptr, wt + 1*16384, pre_g1,     pre_b1,     pre_m1,     pre_v1,     nullptr, A,  5);
    conv_bn_t<0,0><<<4096, 256, CONV_SMEM>>>(A,  nullptr, nullptr, nullptr, wt + 2*16384, pre_g2,     pre_b2,     pre_m2,     pre_v2,     Bb,      Bb, 5);
    conv_bn_t<0,0><<<4096, 256, CONV_SMEM>>>(Bb, nullptr, nullptr, nullptr, wt + 3*16384, pre_g1+128, pre_b1+128, pre_m1+128, pre_v1+128, nullptr, A,  5);
    // last pre conv: maxpool fused into epilogue, writes P directly
    conv_bn_t<0,1><<<4096, 256, CONV_SMEM>>>(A,  nullptr, nullptr, nullptr, wt + 4*16384, pre_g2+128, pre_b2+128, pre_m2+128, pre_v2+128, Bb,      P,  5);

    // pos: 2 res-blocks on (8,128,2048); 16384 cols, kls=11
    conv_bn_t<0,0><<<128, 256, CONV_SMEM>>>(P, nullptr, nullptr, nullptr, wt + 5*16384, pos_g1,     pos_b1,     pos_m1,     pos_v1,     nullptr, D,     11);
    conv_bn_t<0,0><<<128, 256, CONV_SMEM>>>(D, nullptr, nullptr, nullptr, wt + 6*16384, pos_g2,     pos_b2,     pos_m2,     pos_v2,     P,       P,     11);
    conv_bn_t<0,0><<<128, 256, CONV_SMEM>>>(P, nullptr, nullptr, nullptr, wt + 7*16384, pos_g1+128, pos_b1+128, pos_m1+128, pos_v1+128, nullptr, D,     11);
    conv_bn_t<0,0><<<128, 256, CONV_SMEM>>>(D, nullptr, nullptr, nullptr, wt + 8*16384, pos_g2+128, pos_b2+128, pos_m2+128, pos_v2+128, P,       out_x, 11);
}

// round 16
// speedup vs baseline: 1.1190x; 1.1190x over previous
#include <cuda_runtime.h>

#define BATCH   8
#define NPTS    8192
#define CIN     64
#define CMID    128
#define NSAMP   2048
#define KNNK    32
#define NGRP    (BATCH*NSAMP)        /* 16384 */
#define GELEMS  (CMID*KNNK)          /* 4096  */
#define PELEMS  (CMID*NSAMP)         /* 262144 */

#define XS_STRIDE 132                /* padded row stride (floats) */

// -------- scratch (static device globals; no allocation APIs) --------
__device__ float  g_bufA[(size_t)NGRP * GELEMS];   // 268 MB
__device__ float  g_bufB[(size_t)NGRP * GELEMS];   // 268 MB
__device__ float  g_bufP[(size_t)BATCH * PELEMS];  // 8.4 MB
__device__ float  g_bufD[(size_t)BATCH * PELEMS];  // 8.4 MB
__device__ int    g_fps[NGRP];
__device__ int    g_knn[NGRP * KNNK];
__device__ float  g_wtT[9 * 16384];                // transposed weights [s][c][o]

// Bit-exact match to XLA's un-contracted  (dx*dx + dy*dy) + dz*dz
__device__ __forceinline__ float sqdist(float dx, float dy, float dz)
{
    float a = __fmul_rn(dx, dx);
    float b = __fmul_rn(dy, dy);
    float c = __fmul_rn(dz, dz);
    return __fadd_rn(__fadd_rn(a, b), c);
}

__device__ __forceinline__ unsigned redux_max_u32(unsigned v)
{
    unsigned r;
    asm("redux.sync.max.u32 %0, %1, 0xffffffff;" : "=r"(r) : "r"(v));
    return r;
}

#define FFMA2(acc, a, b) \
    asm("fma.rn.f32x2 %0, %1, %2, %3;" : "=l"(acc) : "l"(a), "l"(b), "l"(acc))
#define ADD2(d, a, b) \
    asm("add.rn.f32x2 %0, %1, %2;" : "=l"(d) : "l"(a), "l"(b))
#define MUL2(d, a, b) \
    asm("mul.rn.f32x2 %0, %1, %2;" : "=l"(d) : "l"(a), "l"(b))
#define PACK2(d, lo, hi) \
    asm("mov.b64 %0, {%1, %2};" : "=l"(d) : "r"(__float_as_uint(lo)), "r"(__float_as_uint(hi)))
#define PACKDUP(d, f) \
    asm("mov.b64 %0, {%1, %1};" : "=l"(d) : "r"(__float_as_uint(f)))
#define UNPACK64(lo, hi, v) \
    asm("mov.b64 {%0, %1}, %2;" : "=r"(lo), "=r"(hi) : "l"(v))

// ====================================================================
// Weight pre-transform: WtT[s][c][o] = W_s[o][c]
// ====================================================================
struct WPtrs { const float* w[9]; };
__global__ __launch_bounds__(256) void wtrans_kernel(WPtrs p, float* __restrict__ out)
{
    int idx = blockIdx.x * 256 + threadIdx.x;         // 9*16384 total
    int s = idx >> 14, r = idx & 16383;
    int o = r >> 7, c = r & 127;
    out[(s << 14) + c * 128 + o] = p.w[s][o * 128 + c];
}

// ====================================================================
// FPS: one block/batch, 512 threads, 16 pts/thread (8 packed slots),
// 1 barrier/step. Packed f32x2 distance math (bit-exact). R15-proven.
// ====================================================================
__global__ __launch_bounds__(512) void fps_kernel(const float* __restrict__ xyz,
                                                  float* __restrict__ newxyz,
                                                  int* __restrict__ fpsIdx)
{
    extern __shared__ float fsm[];
    float* sx = fsm;
    float* sy = fsm + NPTS;
    float* sz = fsm + 2*NPTS;
    float* s_val2 = fsm + 3*NPTS;           // [2][16]
    int*   s_idx2 = (int*)(fsm + 3*NPTS + 32);

    const int b = blockIdx.x;
    const int t = threadIdx.x;
    const int lane = t & 31;
    const int warp = t >> 5;                // 0..15
    const float* base = xyz + (size_t)b * NPTS * 3;

    unsigned long long ppx[8], ppy[8], ppz[8], pdd[8];
    float fx0 = 0.f, fy0 = 0.f, fz0 = 0.f;
#pragma unroll
    for (int u = 0; u < 8; u++) {
        int p0 = (2*u) * 512 + t;
        int p1 = (2*u + 1) * 512 + t;
        float x0 = base[p0*3+0], y0 = base[p0*3+1], z0 = base[p0*3+2];
        float x1 = base[p1*3+0], y1 = base[p1*3+1], z1 = base[p1*3+2];
        PACK2(ppx[u], x0, x1);
        PACK2(ppy[u], y0, y1);
        PACK2(ppz[u], z0, z1);
        sx[p0] = x0; sy[p0] = y0; sz[p0] = z0;
        sx[p1] = x1; sy[p1] = y1; sz[p1] = z1;
        PACKDUP(pdd[u], 1e10f);
        if (u == 0) { fx0 = x0; fy0 = y0; fz0 = z0; }
    }

    if (t == 0) {
        fpsIdx[b*NSAMP] = 0;
        newxyz[(size_t)b*NSAMP*3 + 0] = fx0;
        newxyz[(size_t)b*NSAMP*3 + 1] = fy0;
        newxyz[(size_t)b*NSAMP*3 + 2] = fz0;
    }
    __syncthreads();

    int w = 0;
    for (int s = 1; s < NSAMP; s++) {
        unsigned long long nqx2, nqy2, nqz2;
        {
            float nqx = -sx[w], nqy = -sy[w], nqz = -sz[w];
            PACKDUP(nqx2, nqx); PACKDUP(nqy2, nqy); PACKDUP(nqz2, nqz);
        }
        float bv = -1.0f; int bj = 0;
#pragma unroll
        for (int u = 0; u < 8; u++) {
            unsigned long long dx, dy, dz, ss;
            ADD2(dx, ppx[u], nqx2);       // px - qx
            ADD2(dy, ppy[u], nqy2);
            ADD2(dz, ppz[u], nqz2);
            MUL2(dx, dx, dx);
            MUL2(dy, dy, dy);
            MUL2(dz, dz, dz);
            ADD2(ss, dx, dy);
            ADD2(ss, ss, dz);
            unsigned d0b, d1b, e0b, e1b;
            UNPACK64(d0b, d1b, ss);
            UNPACK64(e0b, e1b, pdd[u]);
            float e0 = fminf(__uint_as_float(e0b), __uint_as_float(d0b));
            float e1 = fminf(__uint_as_float(e1b), __uint_as_float(d1b));
            PACK2(pdd[u], e0, e1);
            if (e0 > bv) { bv = e0; bj = 2*u; }
            if (e1 > bv) { bv = e1; bj = 2*u + 1; }
        }
        int gi = (bj << 9) | t;
        unsigned ub = __float_as_uint(bv);
        unsigned mx = redux_max_u32(ub);
        unsigned bl = __ballot_sync(0xffffffffu, ub == mx);
        int src = __ffs(bl) - 1;
        int wgi = __shfl_sync(0xffffffffu, gi, src);

        const int par = (s & 1) * 16;
        if (lane == 0) { s_val2[par + warp] = __uint_as_float(mx); s_idx2[par + warp] = wgi; }
        __syncthreads();

        unsigned v2 = (lane < 16) ? __float_as_uint(s_val2[par + lane]) : 0u;
        int      i2 = (lane < 16) ? s_idx2[par + lane] : 0;
        unsigned m2 = redux_max_u32(v2);
        unsigned b2 = __ballot_sync(0xffffffffu, v2 == m2);
        int s2 = __ffs(b2) - 1;
        w = __shfl_sync(0xffffffffu, i2, s2);

        if (t == 0) {
            fpsIdx[b*NSAMP + s] = w;
            size_t o = ((size_t)b*NSAMP + s)*3;
            newxyz[o+0] = sx[w]; newxyz[o+1] = sy[w]; newxyz[o+2] = sz[w];
        }
    }
}

// ====================================================================
// KNN: 256 blocks, warp-per-sample sorted top-32.
// ====================================================================
__global__ __launch_bounds__(256) void knn_kernel(const float* __restrict__ xyz,
                                                  const float* __restrict__ newxyz,
                                                  int* __restrict__ knnIdx)
{
    extern __shared__ float sm[];
    float* sx = sm; float* sy = sm + NPTS; float* sz = sm + 2*NPTS;
    const int b    = blockIdx.x >> 5;
    const int tile = blockIdx.x & 31;
    const float* base = xyz + (size_t)b * NPTS * 3;
    for (int i = threadIdx.x; i < NPTS; i += 256) {
        sx[i] = base[i*3+0]; sy[i] = base[i*3+1]; sz[i] = base[i*3+2];
    }
    __syncthreads();

    const int lane = threadIdx.x & 31;
    const int warp = threadIdx.x >> 5;

    for (int rep = 0; rep < 8; rep++) {
        const int s = tile*64 + warp*8 + rep;
        const float* q = newxyz + ((size_t)b*NSAMP + s)*3;
        const float qx = q[0], qy = q[1], qz = q[2];
        float lval = 1e30f; int lidx = 0;
        float thr  = 1e30f;

        for (int j0 = 0; j0 < NPTS/32; j0++) {
            const int p = j0*32 + lane;
            float d = sqdist(sx[p]-qx, sy[p]-qy, sz[p]-qz);
            unsigned m = __ballot_sync(0xffffffffu, d < thr);
            if (m) {
                while (m) {
                    int src = __ffs(m) - 1; m &= m - 1;
                    float cd = __shfl_sync(0xffffffffu, d, src);
                    int   cj = __shfl_sync(0xffffffffu, p, src);
                    float pv = __shfl_up_sync(0xffffffffu, lval, 1);
                    int   pi = __shfl_up_sync(0xffffffffu, lidx, 1);
                    bool shift  = lval > cd;
                    bool pshift = (lane > 0) && (pv > cd);
                    lval = shift ? (pshift ? pv : cd) : lval;
                    lidx = shift ? (pshift ? pi : cj) : lidx;
                }
                thr = __shfl_sync(0xffffffffu, lval, 31);
            }
        }
        knnIdx[((size_t)b*NSAMP + s)*KNNK + lane] = lidx;
    }
}

// ====================================================================
// Fused conv1x1 + BN + (residual) + ReLU. FFMA2 col-pairs (R14 form):
// W staged in smem un-duplicated (64-row halves), PACKDUP at use.
// Thread tx=tid&15 owns cols {tx*4..+3} and {64+tx*4..+3}; ty=tid>>4.
// ====================================================================
template<int GATHER, int POOL>
__global__ __launch_bounds__(256, 2) void conv_bn_t(
    const float* __restrict__ X,
    const float* __restrict__ feat, const int* __restrict__ knnIdx, const int* __restrict__ fpsIdx,
    const float* __restrict__ WtT,
    const float* __restrict__ gam, const float* __restrict__ bet,
    const float* __restrict__ mu,  const float* __restrict__ var,
    const float* __restrict__ R,   float* __restrict__ Y,
    int kls)
{
    extern __shared__ float sm[];
    float* Xs      = sm;                       // [128][132]
    float* Ws      = sm + 128*XS_STRIDE;       // [64][128] current W half
    float* s_scale = Ws + 64*128;
    float* s_shift = s_scale + 128;

    const int tid  = threadIdx.x;
    const int klen = 1 << kls;
    const int n0   = blockIdx.x << 7;

    if (GATHER) {
        const int gbase = n0 >> 5;                  // kls == 5 in gather mode
        const int b = gbase >> 11;
        const float* fb = feat + (size_t)b * NPTS * CIN;
        const int cc = tid & 63, jj = tid >> 6;
        for (int it = 0; it < 32; it++) {
            int col = it*4 + jj;
            int g = gbase + (col >> 5), k = col & 31;
            int p = __ldg(&knnIdx[g*KNNK + k]);
            Xs[cc*XS_STRIDE + col] = fb[p*CIN + cc];
        }
        {
            int g = gbase + jj;
            float v = fb[__ldg(&fpsIdx[g])*CIN + cc];
            float4* row = (float4*)(Xs + (cc + CIN)*XS_STRIDE + jj*32);
            float4 vv = make_float4(v, v, v, v);
#pragma unroll
            for (int k4 = 0; k4 < 8; k4++) row[k4] = vv;
        }
    } else {
        for (int idx = tid; idx < 16384; idx += 256) {
            int c = idx >> 7, col = idx & 127;
            int n = n0 + col;
            int g = n >> kls, k = n & (klen-1);
            Xs[c*XS_STRIDE + col] = X[((g << 7) + c) * klen + k];
        }
    }
    if (tid < 128) {
        float sc = gam[tid] / sqrtf(var[tid] + 1e-5f);
        s_scale[tid] = sc;
        s_shift[tid] = bet[tid] - mu[tid] * sc;
    }

    const int tx = tid & 15, ty = tid >> 4;
    unsigned long long acc[8][4];               // [o][colpair]
#pragma unroll
    for (int i = 0; i < 8; i++)
#pragma unroll
        for (int j = 0; j < 4; j++) acc[i][j] = 0ull;

    const float* XsC = Xs + tx*4;

    for (int h = 0; h < 2; h++) {
        __syncthreads();     // h=0: covers X/scale writes; h=1: protects Ws reuse
        {   // stage W half: rows h*64 .. h*64+63 (8192 floats, coalesced)
            const float4* src = (const float4*)(WtT + h*64*128);
            float4*       dst = (float4*)Ws;
#pragma unroll
            for (int i = 0; i < 8; i++) dst[tid + i*256] = src[tid + i*256];
        }
        __syncthreads();

#pragma unroll 2
        for (int kc2 = 0; kc2 < 64; kc2++) {
            const int kc = h*64 + kc2;
            ulonglong2 xa = *(const ulonglong2*)(XsC + kc*XS_STRIDE);        // cols tx*4..+3
            ulonglong2 xb = *(const ulonglong2*)(XsC + kc*XS_STRIDE + 64);   // cols 64+tx*4..+3
            const float* wrow = Ws + kc2*128 + ty*8;
            float4 wA = *(const float4*)(wrow);
            float4 wB = *(const float4*)(wrow + 4);
            unsigned long long wv[8];
            PACKDUP(wv[0], wA.x); PACKDUP(wv[1], wA.y);
            PACKDUP(wv[2], wA.z); PACKDUP(wv[3], wA.w);
            PACKDUP(wv[4], wB.x); PACKDUP(wv[5], wB.y);
            PACKDUP(wv[6], wB.z); PACKDUP(wv[7], wB.w);
            unsigned long long xp[4] = {xa.x, xa.y, xb.x, xb.y};
#pragma unroll
            for (int i = 0; i < 8; i++)
#pragma unroll
                for (int j = 0; j < 4; j++)
                    FFMA2(acc[i][j], wv[i], xp[j]);
        }
    }

    const int ncolA = n0 + tx*4;
    const int ncolB = ncolA + 64;
    const int gA = ncolA >> kls, kA = ncolA & (klen-1);
    const int gB = ncolB >> kls, kB = ncolB & (klen-1);
#pragma unroll
    for (int i = 0; i < 8; i++) {
        const int o = ty*8 + i;
        const float sc = s_scale[o], sh = s_shift[o];
        const int addrA = ((gA << 7) + o) * klen + kA;
        const int addrB = ((gB << 7) + o) * klen + kB;
        float v[8];
#pragma unroll
        for (int j = 0; j < 4; j++) {
            unsigned lo, hi;
            UNPACK64(lo, hi, acc[i][j]);
            v[2*j]   = __uint_as_float(lo);
            v[2*j+1] = __uint_as_float(hi);
        }
#pragma unroll
        for (int j = 0; j < 8; j++) v[j] = fmaf(v[j], sc, sh);
        if (R) {
            float4 rA = *(const float4*)(R + addrA);
            float4 rB = *(const float4*)(R + addrB);
            v[0]+=rA.x; v[1]+=rA.y; v[2]+=rA.z; v[3]+=rA.w;
            v[4]+=rB.x; v[5]+=rB.y; v[6]+=rB.z; v[7]+=rB.w;
        }
#pragma unroll
        for (int j = 0; j < 8; j++) v[j] = fmaxf(v[j], 0.f);

        if (POOL) {
            // klen==32: group A = 32 cols covered by tx-octet {0-7} or {8-15}
            float mA = fmaxf(fmaxf(v[0],v[1]), fmaxf(v[2],v[3]));
            float mB = fmaxf(fmaxf(v[4],v[5]), fmaxf(v[6],v[7]));
            mA = fmaxf(mA, __shfl_xor_sync(0xffffffffu, mA, 1));
            mB = fmaxf(mB, __shfl_xor_sync(0xffffffffu, mB, 1));
            mA = fmaxf(mA, __shfl_xor_sync(0xffffffffu, mA, 2));
            mB = fmaxf(mB, __shfl_xor_sync(0xffffffffu, mB, 2));
            mA = fmaxf(mA, __shfl_xor_sync(0xffffffffu, mA, 4));
            mB = fmaxf(mB, __shfl_xor_sync(0xffffffffu, mB, 4));
            if ((tx & 7) == 0) {
                int bbA = gA >> 11, sA = gA & 2047;
                int bbB = gB >> 11, sB = gB & 2047;
                Y[((bbA << 7) + o) * 2048 + sA] = mA;
                Y[((bbB << 7) + o) * 2048 + sB] = mB;
            }
        } else {
            *(float4*)(Y + addrA) = make_float4(v[0],v[1],v[2],v[3]);
            *(float4*)(Y + addrB) = make_float4(v[4],v[5],v[6],v[7]);
        }
    }
}

// ====================================================================
extern "C" void kernel_launch(void* const* d_in, const int* in_sizes, int n_in,
                              void* d_out, int out_size)
{
    // setup_inputs() dict-insertion order
    const float* xyz    = (const float*)d_in[0];
    const float* feat   = (const float*)d_in[1];
    const float* te_w   = (const float*)d_in[2];
    const float* te_g   = (const float*)d_in[3];
    const float* te_b   = (const float*)d_in[4];
    const float* te_m   = (const float*)d_in[5];
    const float* te_v   = (const float*)d_in[6];
    const float* pre_w1 = (const float*)d_in[7];
    const float* pre_w2 = (const float*)d_in[8];
    const float* pre_g1 = (const float*)d_in[9];
    const float* pre_g2 = (const float*)d_in[10];
    const float* pre_b1 = (const float*)d_in[11];
    const float* pre_b2 = (const float*)d_in[12];
    const float* pre_m1 = (const float*)d_in[13];
    const float* pre_m2 = (const float*)d_in[14];
    const float* pre_v1 = (const float*)d_in[15];
    const float* pre_v2 = (const float*)d_in[16];
    const float* pos_w1 = (const float*)d_in[17];
    const float* pos_w2 = (const float*)d_in[18];
    const float* pos_g1 = (const float*)d_in[19];
    const float* pos_g2 = (const float*)d_in[20];
    const float* pos_b1 = (const float*)d_in[21];
    const float* pos_b2 = (const float*)d_in[22];
    const float* pos_m1 = (const float*)d_in[23];
    const float* pos_m2 = (const float*)d_in[24];
    const float* pos_v1 = (const float*)d_in[25];
    const float* pos_v2 = (const float*)d_in[26];

    float* out_xyz = (float*)d_out;                    // (8,2048,3)
    float* out_x   = (float*)d_out + BATCH*NSAMP*3;    // (8,128,2048)

    float *A, *Bb, *P, *D, *wt; int *fp, *kn;
    cudaGetSymbolAddress((void**)&A,  g_bufA);
    cudaGetSymbolAddress((void**)&Bb, g_bufB);
    cudaGetSymbolAddress((void**)&P,  g_bufP);
    cudaGetSymbolAddress((void**)&D,  g_bufD);
    cudaGetSymbolAddress((void**)&fp, g_fps);
    cudaGetSymbolAddress((void**)&kn, g_knn);
    cudaGetSymbolAddress((void**)&wt, g_wtT);

    const int FPS_SMEM  = (3*NPTS + 64) * 4;                    // ~98.5 KB
    const int KNN_SMEM  = 3 * NPTS * 4;                         // 96 KB
    const int CONV_SMEM = (128*XS_STRIDE + 64*128 + 256) * 4;   // ~99 KB
    cudaFuncSetAttribute(fps_kernel,      cudaFuncAttributeMaxDynamicSharedMemorySize, FPS_SMEM);
    cudaFuncSetAttribute(knn_kernel,      cudaFuncAttributeMaxDynamicSharedMemorySize, KNN_SMEM);
    cudaFuncSetAttribute(conv_bn_t<0,0>,  cudaFuncAttributeMaxDynamicSharedMemorySize, CONV_SMEM);
    cudaFuncSetAttribute(conv_bn_t<1,0>,  cudaFuncAttributeMaxDynamicSharedMemorySize, CONV_SMEM);
    cudaFuncSetAttribute(conv_bn_t<0,1>,  cudaFuncAttributeMaxDynamicSharedMemorySize, CONV_SMEM);

    // weight pre-transform (stage order: te, pw1[0], pw2[0], pw1[1], pw2[1], qw1[0], qw2[0], qw1[1], qw2[1])
    WPtrs wp;
    wp.w[0] = te_w;
    wp.w[1] = pre_w1;          wp.w[2] = pre_w2;
    wp.w[3] = pre_w1 + 16384;  wp.w[4] = pre_w2 + 16384;
    wp.w[5] = pos_w1;          wp.w[6] = pos_w2;
    wp.w[7] = pos_w1 + 16384;  wp.w[8] = pos_w2 + 16384;
    wtrans_kernel<<<(9*16384)/256, 256>>>(wp, wt);

    fps_kernel<<<BATCH, 512, FPS_SMEM>>>(xyz, out_xyz, fp);
    knn_kernel<<<256, 256, KNN_SMEM>>>(xyz, out_xyz, kn);

    // te (gather fused) + 2 pre res-blocks; 524288 cols, kls=5
    conv_bn_t<1,0><<<4096, 256, CONV_SMEM>>>(nullptr, feat, kn, fp, wt + 0*16384, te_g, te_b, te_m, te_v, nullptr, Bb, 5);
    conv_bn_t<0,0><<<4096, 256, CONV_SMEM>>>(Bb, nullptr, nullptr, nullptr, wt + 1*16384, pre_g1,     pre_b1,     pre_m1,     pre_v1,     nullptr, A,  5);
    conv_bn_t<0,0><<<4096, 256, CONV_SMEM>>>(A,  nullptr, nullptr, nullptr, wt + 2*16384, pre_g2,     pre_b2,     pre_m2,     pre_v2,     Bb,      Bb, 5);
    conv_bn_t<0,0><<<4096, 256, CONV_SMEM>>>(Bb, nullptr, nullptr, nullptr, wt + 3*16384, pre_g1+128, pre_b1+128, pre_m1+128, pre_v1+128, nullptr, A,  5);
    // last pre conv: maxpool fused into epilogue, writes P directly
    conv_bn_t<0,1><<<4096, 256, CONV_SMEM>>>(A,  nullptr, nullptr, nullptr, wt + 4*16384, pre_g2+128, pre_b2+128, pre_m2+128, pre_v2+128, Bb,      P,  5);

    // pos: 2 res-blocks on (8,128,2048); 16384 cols, kls=11
    conv_bn_t<0,0><<<128, 256, CONV_SMEM>>>(P, nullptr, nullptr, nullptr, wt + 5*16384, pos_g1,     pos_b1,     pos_m1,     pos_v1,     nullptr, D,     11);
    conv_bn_t<0,0><<<128, 256, CONV_SMEM>>>(D, nullptr, nullptr, nullptr, wt + 6*16384, pos_g2,     pos_b2,     pos_m2,     pos_v2,     P,       P,     11);
    conv_bn_t<0,0><<<128, 256, CONV_SMEM>>>(P, nullptr, nullptr, nullptr, wt + 7*16384, pos_g1+128, pos_b1+128, pos_m1+128, pos_v1+128, nullptr, D,     11);
    conv_bn_t<0,0><<<128, 256, CONV_SMEM>>>(D, nullptr, nullptr, nullptr, wt + 8*16384, pos_g2+128, pos_b2+128, pos_m2+128, pos_v2+128, P,       out_x, 11);
}

// round 17
// speedup vs baseline: 1.2283x; 1.0978x over previous
#include <cuda_runtime.h>

#define BATCH   8
#define NPTS    8192
#define CIN     64
#define CMID    128
#define NSAMP   2048
#define KNNK    32
#define NGRP    (BATCH*NSAMP)        /* 16384 */
#define PELEMS  (CMID*NSAMP)         /* 262144 */

#define XS_STRIDE 132                /* padded row stride (floats) */

// -------- scratch (static device globals; no allocation APIs) --------
__device__ float  g_bufP[(size_t)BATCH * PELEMS];  // 8.4 MB
__device__ float  g_bufD[(size_t)BATCH * PELEMS];  // 8.4 MB
__device__ int    g_fps[NGRP];
__device__ int    g_knn[NGRP * KNNK];
__device__ float  g_wtT[9 * 16384];                // transposed weights [s][c][o]

// Bit-exact match to XLA's un-contracted  (dx*dx + dy*dy) + dz*dz
__device__ __forceinline__ float sqdist(float dx, float dy, float dz)
{
    float a = __fmul_rn(dx, dx);
    float b = __fmul_rn(dy, dy);
    float c = __fmul_rn(dz, dz);
    return __fadd_rn(__fadd_rn(a, b), c);
}

__device__ __forceinline__ unsigned redux_max_u32(unsigned v)
{
    unsigned r;
    asm("redux.sync.max.u32 %0, %1, 0xffffffff;" : "=r"(r) : "r"(v));
    return r;
}

#define FFMA2(acc, a, b) \
    asm("fma.rn.f32x2 %0, %1, %2, %3;" : "=l"(acc) : "l"(a), "l"(b), "l"(acc))
#define ADD2(d, a, b) \
    asm("add.rn.f32x2 %0, %1, %2;" : "=l"(d) : "l"(a), "l"(b))
#define MUL2(d, a, b) \
    asm("mul.rn.f32x2 %0, %1, %2;" : "=l"(d) : "l"(a), "l"(b))
#define PACK2(d, lo, hi) \
    asm("mov.b64 %0, {%1, %2};" : "=l"(d) : "r"(__float_as_uint(lo)), "r"(__float_as_uint(hi)))
#define PACKDUP(d, f) \
    asm("mov.b64 %0, {%1, %1};" : "=l"(d) : "r"(__float_as_uint(f)))
#define UNPACK64(lo, hi, v) \
    asm("mov.b64 {%0, %1}, %2;" : "=r"(lo), "=r"(hi) : "l"(v))

// ====================================================================
// Weight pre-transform: WtT[s][c][o] = W_s[o][c]
// ====================================================================
struct WPtrs { const float* w[9]; };
__global__ __launch_bounds__(256) void wtrans_kernel(WPtrs p, float* __restrict__ out)
{
    int idx = blockIdx.x * 256 + threadIdx.x;         // 9*16384 total
    int s = idx >> 14, r = idx & 16383;
    int o = r >> 7, c = r & 127;
    out[(s << 14) + c * 128 + o] = p.w[s][o * 128 + c];
}

// ====================================================================
// FPS: one block/batch, 512 threads, 16 pts/thread (8 packed slots),
// 1 barrier/step. Packed f32x2 distance math (bit-exact). R15-proven.
// ====================================================================
__global__ __launch_bounds__(512) void fps_kernel(const float* __restrict__ xyz,
                                                  float* __restrict__ newxyz,
                                                  int* __restrict__ fpsIdx)
{
    extern __shared__ float fsm[];
    float* sx = fsm;
    float* sy = fsm + NPTS;
    float* sz = fsm + 2*NPTS;
    float* s_val2 = fsm + 3*NPTS;           // [2][16]
    int*   s_idx2 = (int*)(fsm + 3*NPTS + 32);

    const int b = blockIdx.x;
    const int t = threadIdx.x;
    const int lane = t & 31;
    const int warp = t >> 5;                // 0..15
    const float* base = xyz + (size_t)b * NPTS * 3;

    unsigned long long ppx[8], ppy[8], ppz[8], pdd[8];
    float fx0 = 0.f, fy0 = 0.f, fz0 = 0.f;
#pragma unroll
    for (int u = 0; u < 8; u++) {
        int p0 = (2*u) * 512 + t;
        int p1 = (2*u + 1) * 512 + t;
        float x0 = base[p0*3+0], y0 = base[p0*3+1], z0 = base[p0*3+2];
        float x1 = base[p1*3+0], y1 = base[p1*3+1], z1 = base[p1*3+2];
        PACK2(ppx[u], x0, x1);
        PACK2(ppy[u], y0, y1);
        PACK2(ppz[u], z0, z1);
        sx[p0] = x0; sy[p0] = y0; sz[p0] = z0;
        sx[p1] = x1; sy[p1] = y1; sz[p1] = z1;
        PACKDUP(pdd[u], 1e10f);
        if (u == 0) { fx0 = x0; fy0 = y0; fz0 = z0; }
    }

    if (t == 0) {
        fpsIdx[b*NSAMP] = 0;
        newxyz[(size_t)b*NSAMP*3 + 0] = fx0;
        newxyz[(size_t)b*NSAMP*3 + 1] = fy0;
        newxyz[(size_t)b*NSAMP*3 + 2] = fz0;
    }
    __syncthreads();

    int w = 0;
    for (int s = 1; s < NSAMP; s++) {
        unsigned long long nqx2, nqy2, nqz2;
        {
            float nqx = -sx[w], nqy = -sy[w], nqz = -sz[w];
            PACKDUP(nqx2, nqx); PACKDUP(nqy2, nqy); PACKDUP(nqz2, nqz);
        }
        float bv = -1.0f; int bj = 0;
#pragma unroll
        for (int u = 0; u < 8; u++) {
            unsigned long long dx, dy, dz, ss;
            ADD2(dx, ppx[u], nqx2);       // px - qx
            ADD2(dy, ppy[u], nqy2);
            ADD2(dz, ppz[u], nqz2);
            MUL2(dx, dx, dx);
            MUL2(dy, dy, dy);
            MUL2(dz, dz, dz);
            ADD2(ss, dx, dy);
            ADD2(ss, ss, dz);
            unsigned d0b, d1b, e0b, e1b;
            UNPACK64(d0b, d1b, ss);
            UNPACK64(e0b, e1b, pdd[u]);
            float e0 = fminf(__uint_as_float(e0b), __uint_as_float(d0b));
            float e1 = fminf(__uint_as_float(e1b), __uint_as_float(d1b));
            PACK2(pdd[u], e0, e1);
            if (e0 > bv) { bv = e0; bj = 2*u; }
            if (e1 > bv) { bv = e1; bj = 2*u + 1; }
        }
        int gi = (bj << 9) | t;
        unsigned ub = __float_as_uint(bv);
        unsigned mx = redux_max_u32(ub);
        unsigned bl = __ballot_sync(0xffffffffu, ub == mx);
        int src = __ffs(bl) - 1;
        int wgi = __shfl_sync(0xffffffffu, gi, src);

        const int par = (s & 1) * 16;
        if (lane == 0) { s_val2[par + warp] = __uint_as_float(mx); s_idx2[par + warp] = wgi; }
        __syncthreads();

        unsigned v2 = (lane < 16) ? __float_as_uint(s_val2[par + lane]) : 0u;
        int      i2 = (lane < 16) ? s_idx2[par + lane] : 0;
        unsigned m2 = redux_max_u32(v2);
        unsigned b2 = __ballot_sync(0xffffffffu, v2 == m2);
        int s2 = __ffs(b2) - 1;
        w = __shfl_sync(0xffffffffu, i2, s2);

        if (t == 0) {
            fpsIdx[b*NSAMP + s] = w;
            size_t o = ((size_t)b*NSAMP + s)*3;
            newxyz[o+0] = sx[w]; newxyz[o+1] = sy[w]; newxyz[o+2] = sz[w];
        }
    }
}

// ====================================================================
// KNN: 256 blocks, warp-per-sample sorted top-32.
// ====================================================================
__global__ __launch_bounds__(256) void knn_kernel(const float* __restrict__ xyz,
                                                  const float* __restrict__ newxyz,
                                                  int* __restrict__ knnIdx)
{
    extern __shared__ float sm[];
    float* sx = sm; float* sy = sm + NPTS; float* sz = sm + 2*NPTS;
    const int b    = blockIdx.x >> 5;
    const int tile = blockIdx.x & 31;
    const float* base = xyz + (size_t)b * NPTS * 3;
    for (int i = threadIdx.x; i < NPTS; i += 256) {
        sx[i] = base[i*3+0]; sy[i] = base[i*3+1]; sz[i] = base[i*3+2];
    }
    __syncthreads();

    const int lane = threadIdx.x & 31;
    const int warp = threadIdx.x >> 5;

    for (int rep = 0; rep < 8; rep++) {
        const int s = tile*64 + warp*8 + rep;
        const float* q = newxyz + ((size_t)b*NSAMP + s)*3;
        const float qx = q[0], qy = q[1], qz = q[2];
        float lval = 1e30f; int lidx = 0;
        float thr  = 1e30f;

        for (int j0 = 0; j0 < NPTS/32; j0++) {
            const int p = j0*32 + lane;
            float d = sqdist(sx[p]-qx, sy[p]-qy, sz[p]-qz);
            unsigned m = __ballot_sync(0xffffffffu, d < thr);
            if (m) {
                while (m) {
                    int src = __ffs(m) - 1; m &= m - 1;
                    float cd = __shfl_sync(0xffffffffu, d, src);
                    int   cj = __shfl_sync(0xffffffffu, p, src);
                    float pv = __shfl_up_sync(0xffffffffu, lval, 1);
                    int   pi = __shfl_up_sync(0xffffffffu, lidx, 1);
                    bool shift  = lval > cd;
                    bool pshift = (lane > 0) && (pv > cd);
                    lval = shift ? (pshift ? pv : cd) : lval;
                    lidx = shift ? (pshift ? pi : cj) : lidx;
                }
                thr = __shfl_sync(0xffffffffu, lval, 31);
            }
        }
        knnIdx[((size_t)b*NSAMP + s)*KNNK + lane] = lidx;
    }
}

// ====================================================================
// FUSED pre-chain: gather -> te -> pre1..pre4 -> maxpool, all in smem.
// 128 cols (4 groups)/CTA, 512 threads, 1 CTA/SM.
// tx=tid&31 (cols tx*4..+3), ty=tid>>5 (o=ty*8..+7, warp-uniform).
// Per thread-kc: 1 X-LDS.128 + 2 W-LDS.128 (broadcast) + 8 PACKDUP
// + 16 FFMA2  (R14-validated operand balance).
// ====================================================================
struct BNP { const float* g[5]; const float* b[5]; const float* m[5]; const float* v[5]; };

__global__ __launch_bounds__(512, 1) void fused_pre_kernel(
    const float* __restrict__ feat, const int* __restrict__ knnIdx,
    const int* __restrict__ fpsIdx, const float* __restrict__ WtT,
    BNP bp, float* __restrict__ P)
{
    extern __shared__ float sm[];
    float* bufA    = sm;                        // [128][132]
    float* bufB    = sm + 128*XS_STRIDE;        // [128][132]
    float* Ws      = sm + 2*128*XS_STRIDE;      // [64][128] W half
    float* s_scale = Ws + 64*128;               // [2][128]
    float* s_shift = s_scale + 256;

    const int tid   = threadIdx.x;
    const int gbase = blockIdx.x * 4;           // 4 groups per CTA
    const int b     = gbase >> 11;
    const float* fb = feat + (size_t)b * NPTS * CIN;

    // ---- gather: neighbor rows c 0..63 into cols 0..127 ----
    const int cc = tid & 63, jj = tid >> 6;     // jj 0..7
#pragma unroll
    for (int it = 0; it < 16; it++) {
        int col = it*8 + jj;
        int g = gbase + (col >> 5), k = col & 31;
        int p = __ldg(&knnIdx[g*KNNK + k]);
        bufA[cc*XS_STRIDE + col] = fb[p*CIN + cc];
    }
    // ---- center rows c 64..127, replicated over each group's 32 cols ----
    if (tid < 256) {
        int grp = tid >> 6;                     // 0..3
        float v = fb[__ldg(&fpsIdx[gbase + grp])*CIN + cc];
        float4 vv = make_float4(v, v, v, v);
        float4* row = (float4*)(bufA + (64 + cc)*XS_STRIDE + grp*32);
#pragma unroll
        for (int k4 = 0; k4 < 8; k4++) row[k4] = vv;
    }

    const int tx = tid & 31, ty = tid >> 5;
    float* bufIn  = bufA;
    float* bufOut = bufB;

    for (int s = 0; s < 5; s++) {
        const int par = (s & 1) << 7;
        if (tid < 128) {
            float sc = bp.g[s][tid] / sqrtf(bp.v[s][tid] + 1e-5f);
            s_scale[par + tid] = sc;
            s_shift[par + tid] = bp.b[s][tid] - bp.m[s][tid] * sc;
        }

        unsigned long long acc[8][2];
#pragma unroll
        for (int i = 0; i < 8; i++) { acc[i][0] = 0ull; acc[i][1] = 0ull; }

        const float* XsC = bufIn + tx*4;
        const float* Wst = WtT + (s << 14);

        for (int h = 0; h < 2; h++) {
            __syncthreads();     // covers prev writes (epilogue/gather/scales) before Ws overwrite
            {   // stage W half: 8192 floats, 2048 float4, 512 threads
                const float4* src = (const float4*)(Wst + h*8192);
                float4*       dst = (float4*)Ws;
#pragma unroll
                for (int i = 0; i < 4; i++) dst[tid + i*512] = src[tid + i*512];
            }
            __syncthreads();

#pragma unroll 2
            for (int kc2 = 0; kc2 < 64; kc2++) {
                const int kc = h*64 + kc2;
                ulonglong2 xa = *(const ulonglong2*)(XsC + kc*XS_STRIDE);   // cols tx*4..+3
                const float* wrow = Ws + kc2*128 + ty*8;                    // warp-uniform
                float4 wA = *(const float4*)(wrow);
                float4 wB = *(const float4*)(wrow + 4);
                unsigned long long wv[8];
                PACKDUP(wv[0], wA.x); PACKDUP(wv[1], wA.y);
                PACKDUP(wv[2], wA.z); PACKDUP(wv[3], wA.w);
                PACKDUP(wv[4], wB.x); PACKDUP(wv[5], wB.y);
                PACKDUP(wv[6], wB.z); PACKDUP(wv[7], wB.w);
                unsigned long long xp[2] = {xa.x, xa.y};
#pragma unroll
                for (int i = 0; i < 8; i++) {
                    FFMA2(acc[i][0], wv[i], xp[0]);
                    FFMA2(acc[i][1], wv[i], xp[1]);
                }
            }
        }

        const bool res  = (s == 2) || (s == 4);
        const bool pool = (s == 4);
#pragma unroll
        for (int i = 0; i < 8; i++) {
            const int o = ty*8 + i;
            const float sc = s_scale[par + o], sh = s_shift[par + o];
            float v[4];
            {
                unsigned l0, h0, l1, h1;
                UNPACK64(l0, h0, acc[i][0]);
                UNPACK64(l1, h1, acc[i][1]);
                v[0] = __uint_as_float(l0); v[1] = __uint_as_float(h0);
                v[2] = __uint_as_float(l1); v[3] = __uint_as_float(h1);
            }
#pragma unroll
            for (int c = 0; c < 4; c++) v[c] = fmaf(v[c], sc, sh);
            if (res) {
                float4 r = *(const float4*)(bufOut + o*XS_STRIDE + tx*4);
                v[0]+=r.x; v[1]+=r.y; v[2]+=r.z; v[3]+=r.w;
            }
#pragma unroll
            for (int c = 0; c < 4; c++) v[c] = fmaxf(v[c], 0.f);

            if (pool) {
                // group = tx>>3; its 32 cols are covered by the tx-octet
                float m = fmaxf(fmaxf(v[0],v[1]), fmaxf(v[2],v[3]));
                m = fmaxf(m, __shfl_xor_sync(0xffffffffu, m, 1));
                m = fmaxf(m, __shfl_xor_sync(0xffffffffu, m, 2));
                m = fmaxf(m, __shfl_xor_sync(0xffffffffu, m, 4));
                if ((tx & 7) == 0) {
                    int g = gbase + (tx >> 3);
                    int bb = g >> 11, ss = g & 2047;
                    P[((bb << 7) + o) * 2048 + ss] = m;
                }
            } else {
                *(float4*)(bufOut + o*XS_STRIDE + tx*4) = make_float4(v[0],v[1],v[2],v[3]);
            }
        }
        float* t2 = bufIn; bufIn = bufOut; bufOut = t2;
    }
}

// ====================================================================
// pos conv (R14/R16-proven): 128-col tile, FFMA2 col-pairs, W smem
// halves + PACKDUP at use. kls=11, no gather/pool.
// ====================================================================
__global__ __launch_bounds__(256, 2) void conv_bn_pos(
    const float* __restrict__ X, const float* __restrict__ WtT,
    const float* __restrict__ gam, const float* __restrict__ bet,
    const float* __restrict__ mu,  const float* __restrict__ var,
    const float* __restrict__ R,   float* __restrict__ Y)
{
    extern __shared__ float sm[];
    float* Xs      = sm;                       // [128][132]
    float* Ws      = sm + 128*XS_STRIDE;       // [64][128]
    float* s_scale = Ws + 64*128;
    float* s_shift = s_scale + 128;

    const int tid  = threadIdx.x;
    const int klen = 2048;
    const int n0   = blockIdx.x << 7;

    for (int idx = tid; idx < 16384; idx += 256) {
        int c = idx >> 7, col = idx & 127;
        int n = n0 + col;
        int g = n >> 11, k = n & (klen-1);
        Xs[c*XS_STRIDE + col] = X[((g << 7) + c) * klen + k];
    }
    if (tid < 128) {
        float sc = gam[tid] / sqrtf(var[tid] + 1e-5f);
        s_scale[tid] = sc;
        s_shift[tid] = bet[tid] - mu[tid] * sc;
    }

    const int tx = tid & 15, ty = tid >> 4;
    unsigned long long acc[8][4];
#pragma unroll
    for (int i = 0; i < 8; i++)
#pragma unroll
        for (int j = 0; j < 4; j++) acc[i][j] = 0ull;

    const float* XsC = Xs + tx*4;

    for (int h = 0; h < 2; h++) {
        __syncthreads();
        {
            const float4* src = (const float4*)(WtT + h*64*128);
            float4*       dst = (float4*)Ws;
#pragma unroll
            for (int i = 0; i < 8; i++) dst[tid + i*256] = src[tid + i*256];
        }
        __syncthreads();

#pragma unroll 2
        for (int kc2 = 0; kc2 < 64; kc2++) {
            const int kc = h*64 + kc2;
            ulonglong2 xa = *(const ulonglong2*)(XsC + kc*XS_STRIDE);
            ulonglong2 xb = *(const ulonglong2*)(XsC + kc*XS_STRIDE + 64);
            const float* wrow = Ws + kc2*128 + ty*8;
            float4 wA = *(const float4*)(wrow);
            float4 wB = *(const float4*)(wrow + 4);
            unsigned long long wv[8];
            PACKDUP(wv[0], wA.x); PACKDUP(wv[1], wA.y);
            PACKDUP(wv[2], wA.z); PACKDUP(wv[3], wA.w);
            PACKDUP(wv[4], wB.x); PACKDUP(wv[5], wB.y);
            PACKDUP(wv[6], wB.z); PACKDUP(wv[7], wB.w);
            unsigned long long xp[4] = {xa.x, xa.y, xb.x, xb.y};
#pragma unroll
            for (int i = 0; i < 8; i++)
#pragma unroll
                for (int j = 0; j < 4; j++)
                    FFMA2(acc[i][j], wv[i], xp[j]);
        }
    }

    const int ncolA = n0 + tx*4;
    const int ncolB = ncolA + 64;
    const int gA = ncolA >> 11, kA = ncolA & (klen-1);
    const int gB = ncolB >> 11, kB = ncolB & (klen-1);
#pragma unroll
    for (int i = 0; i < 8; i++) {
        const int o = ty*8 + i;
        const float sc = s_scale[o], sh = s_shift[o];
        const int addrA = ((gA << 7) + o) * klen + kA;
        const int addrB = ((gB << 7) + o) * klen + kB;
        float v[8];
#pragma unroll
        for (int j = 0; j < 4; j++) {
            unsigned lo, hi;
            UNPACK64(lo, hi, acc[i][j]);
            v[2*j]   = __uint_as_float(lo);
            v[2*j+1] = __uint_as_float(hi);
        }
#pragma unroll
        for (int j = 0; j < 8; j++) v[j] = fmaf(v[j], sc, sh);
        if (R) {
            float4 rA = *(const float4*)(R + addrA);
            float4 rB = *(const float4*)(R + addrB);
            v[0]+=rA.x; v[1]+=rA.y; v[2]+=rA.z; v[3]+=rA.w;
            v[4]+=rB.x; v[5]+=rB.y; v[6]+=rB.z; v[7]+=rB.w;
        }
#pragma unroll
        for (int j = 0; j < 8; j++) v[j] = fmaxf(v[j], 0.f);
        *(float4*)(Y + addrA) = make_float4(v[0],v[1],v[2],v[3]);
        *(float4*)(Y + addrB) = make_float4(v[4],v[5],v[6],v[7]);
    }
}

// ====================================================================
extern "C" void kernel_launch(void* const* d_in, const int* in_sizes, int n_in,
                              void* d_out, int out_size)
{
    // setup_inputs() dict-insertion order
    const float* xyz    = (const float*)d_in[0];
    const float* feat   = (const float*)d_in[1];
    const float* te_w   = (const float*)d_in[2];
    const float* te_g   = (const float*)d_in[3];
    const float* te_b   = (const float*)d_in[4];
    const float* te_m   = (const float*)d_in[5];
    const float* te_v   = (const float*)d_in[6];
    const float* pre_w1 = (const float*)d_in[7];
    const float* pre_w2 = (const float*)d_in[8];
    const float* pre_g1 = (const float*)d_in[9];
    const float* pre_g2 = (const float*)d_in[10];
    const float* pre_b1 = (const float*)d_in[11];
    const float* pre_b2 = (const float*)d_in[12];
    const float* pre_m1 = (const float*)d_in[13];
    const float* pre_m2 = (const float*)d_in[14];
    const float* pre_v1 = (const float*)d_in[15];
    const float* pre_v2 = (const float*)d_in[16];
    const float* pos_w1 = (const float*)d_in[17];
    const float* pos_w2 = (const float*)d_in[18];
    const float* pos_g1 = (const float*)d_in[19];
    const float* pos_g2 = (const float*)d_in[20];
    const float* pos_b1 = (const float*)d_in[21];
    const float* pos_b2 = (const float*)d_in[22];
    const float* pos_m1 = (const float*)d_in[23];
    const float* pos_m2 = (const float*)d_in[24];
    const float* pos_v1 = (const float*)d_in[25];
    const float* pos_v2 = (const float*)d_in[26];

    float* out_xyz = (float*)d_out;                    // (8,2048,3)
    float* out_x   = (float*)d_out + BATCH*NSAMP*3;    // (8,128,2048)

    float *P, *D, *wt; int *fp, *kn;
    cudaGetSymbolAddress((void**)&P,  g_bufP);
    cudaGetSymbolAddress((void**)&D,  g_bufD);
    cudaGetSymbolAddress((void**)&fp, g_fps);
    cudaGetSymbolAddress((void**)&kn, g_knn);
    cudaGetSymbolAddress((void**)&wt, g_wtT);

    const int FPS_SMEM   = (3*NPTS + 64) * 4;                        // ~98.5 KB
    const int KNN_SMEM   = 3 * NPTS * 4;                             // 96 KB
    const int FUSED_SMEM = (2*128*XS_STRIDE + 64*128 + 512) * 4;     // 169,984 B
    const int POS_SMEM   = (128*XS_STRIDE + 64*128 + 256) * 4;       // ~99 KB
    cudaFuncSetAttribute(fps_kernel,       cudaFuncAttributeMaxDynamicSharedMemorySize, FPS_SMEM);
    cudaFuncSetAttribute(knn_kernel,       cudaFuncAttributeMaxDynamicSharedMemorySize, KNN_SMEM);
    cudaFuncSetAttribute(fused_pre_kernel, cudaFuncAttributeMaxDynamicSharedMemorySize, FUSED_SMEM);
    cudaFuncSetAttribute(conv_bn_pos,      cudaFuncAttributeMaxDynamicSharedMemorySize, POS_SMEM);

    // weight pre-transform (stage order: te, pw1[0], pw2[0], pw1[1], pw2[1], qw1[0], qw2[0], qw1[1], qw2[1])
    WPtrs wp;
    wp.w[0] = te_w;
    wp.w[1] = pre_w1;          wp.w[2] = pre_w2;
    wp.w[3] = pre_w1 + 16384;  wp.w[4] = pre_w2 + 16384;
    wp.w[5] = pos_w1;          wp.w[6] = pos_w2;
    wp.w[7] = pos_w1 + 16384;  wp.w[8] = pos_w2 + 16384;
    wtrans_kernel<<<(9*16384)/256, 256>>>(wp, wt);

    fps_kernel<<<BATCH, 512, FPS_SMEM>>>(xyz, out_xyz, fp);
    knn_kernel<<<256, 256, KNN_SMEM>>>(xyz, out_xyz, kn);

    // fused te + pre chain + maxpool: 4096 CTAs x 4 groups
    BNP bp;
    bp.g[0]=te_g;        bp.b[0]=te_b;        bp.m[0]=te_m;        bp.v[0]=te_v;
    bp.g[1]=pre_g1;      bp.b[1]=pre_b1;      bp.m[1]=pre_m1;      bp.v[1]=pre_v1;
    bp.g[2]=pre_g2;      bp.b[2]=pre_b2;      bp.m[2]=pre_m2;      bp.v[2]=pre_v2;
    bp.g[3]=pre_g1+128;  bp.b[3]=pre_b1+128;  bp.m[3]=pre_m1+128;  bp.v[3]=pre_v1+128;
    bp.g[4]=pre_g2+128;  bp.b[4]=pre_b2+128;  bp.m[4]=pre_m2+128;  bp.v[4]=pre_v2+128;
    fused_pre_kernel<<<NGRP/4, 512, FUSED_SMEM>>>(feat, kn, fp, wt, bp, P);

    // pos: 2 res-blocks on (8,128,2048); 16384 cols
    conv_bn_pos<<<128, 256, POS_SMEM>>>(P, wt + 5*16384, pos_g1,     pos_b1,     pos_m1,     pos_v1,     nullptr, D);
    conv_bn_pos<<<128, 256, POS_SMEM>>>(D, wt + 6*16384, pos_g2,     pos_b2,     pos_m2,     pos_v2,     P,       P);
    conv_bn_pos<<<128, 256, POS_SMEM>>>(P, wt + 7*16384, pos_g1+128, pos_b1+128, pos_m1+128, pos_v1+128, nullptr, D);
    conv_bn_pos<<<128, 256, POS_SMEM>>>(D, wt + 8*16384, pos_g2+128, pos_b2+128, pos_m2+128, pos_v2+128, P,       out_x);
}